// round 1
// baseline (speedup 1.0000x reference)
#include <cuda_runtime.h>

// PoseLSTM: 10-layer LSTM, T=1024, B=1024, I=H=10.
// Strategy: layer-wavefront pipeline inside a block.
//   - block = 10 warps, warp w == layer w
//   - each warp owns NB=3 batch elements; lane = (e, u), e in [0,3), u in [0,10)
//   - layers communicate h through double-buffered SMEM, 1 __syncthreads per step
//   - weights live in SMEM (840 floats/layer), vector LDS (float4/float2)
//   - layer 0 prefetches x with distance 2 to cover DRAM latency
// Critical path: T + L - 1 = 1033 steps instead of T*L = 10240.

#define TT 1024
#define BB 1024
#define LL 10
#define HH 10
#define NB 3
#define NTH 320           // 10 warps
#define ROWLEN 28         // per gate row: Wi[0..9], pad, pad, Wh[12..21], pad, pad, bias[24]

__device__ __forceinline__ float sigm(float z)  { return 1.0f / (1.0f + __expf(-z)); }
__device__ __forceinline__ float tanhx(float z) { return 2.0f / (1.0f + __expf(-2.0f * z)) - 1.0f; }

__global__ __launch_bounds__(NTH, 3)
void lstm_pipe(const float* __restrict__ x,   // (T,B,I)
               const float* __restrict__ hp,  // (L,B,H)
               const float* __restrict__ cp,  // (L,B,H)
               const float* __restrict__ Wih, // (L,4H,I)
               const float* __restrict__ Whh, // (L,4H,H)
               const float* __restrict__ bih, // (L,4H)
               const float* __restrict__ bhh, // (L,4H)
               float* __restrict__ out)       // (T,B,H) ++ (L,B,H) ++ (L,B,H)
{
    __shared__ __align__(16) float sW[LL][40][ROWLEN];   // 44800 B
    __shared__ __align__(16) float hio[2][LL][NB][12];   // 2880 B (double-buffered h)

    const int tid = threadIdx.x;

    // ---- stage weights into SMEM ----
    for (int idx = tid; idx < LL * 40 * HH; idx += NTH) {
        int l = idx / 400;
        int rem = idx % 400;
        int r = rem / HH;
        int k = rem % HH;
        sW[l][r][k]      = Wih[idx];
        sW[l][r][12 + k] = Whh[idx];
    }
    for (int idx = tid; idx < LL * 40; idx += NTH) {
        sW[idx / 40][idx % 40][24] = bih[idx] + bhh[idx];
    }

    const int l    = tid >> 5;        // layer == warp id
    const int lane = tid & 31;
    const int e    = lane / HH;       // batch element within warp (0..2)
    const int u    = lane % HH;       // hidden unit (0..9)
    const int b    = blockIdx.x * NB + e;
    const bool active = (lane < 30) && (b < BB);

    // ---- init state ----
    float h = 0.0f, c = 0.0f;
    if (active) {
        h = hp[(l * BB + b) * HH + u];
        c = cp[(l * BB + b) * HH + u];
        hio[l & 1][l][e][u] = h;      // h_{-1} visible at global step s == l
    }

    // ---- layer-0 x prefetch (distance 2) ----
    float xa[HH], xb[HH];
    if (l == 0 && active) {
        const float2* p0 = reinterpret_cast<const float2*>(x + (size_t)b * HH);
        const float2* p1 = reinterpret_cast<const float2*>(x + ((size_t)BB + b) * HH);
#pragma unroll
        for (int k = 0; k < 5; ++k) {
            float2 v = __ldg(p0 + k); xa[2 * k] = v.x; xa[2 * k + 1] = v.y;
            float2 w = __ldg(p1 + k); xb[2 * k] = w.x; xb[2 * k + 1] = w.y;
        }
    }

    const size_t base_hn = (size_t)TT * BB * HH;
    const size_t base_cn = base_hn + (size_t)LL * BB * HH;

    // ---- wavefront main loop ----
    for (int s = 0; s < TT + LL - 1; ++s) {
        __syncthreads();              // orders step s-1 writes before step s reads
        const int t = s - l;          // this warp's local timestep
        if (active && (unsigned)t < (unsigned)TT) {
            // gather layer input x_t^{(l)}
            float xin[HH];
            if (l == 0) {
#pragma unroll
                for (int k = 0; k < HH; ++k) { xin[k] = xa[k]; xa[k] = xb[k]; }
                const int tp = t + 2;
                if (tp < TT) {
                    const float2* pp = reinterpret_cast<const float2*>(
                        x + ((size_t)tp * BB + b) * HH);
#pragma unroll
                    for (int k = 0; k < 5; ++k) {
                        float2 v = __ldg(pp + k);
                        xb[2 * k] = v.x; xb[2 * k + 1] = v.y;
                    }
                }
            } else {
                const float4* q = reinterpret_cast<const float4*>(&hio[s & 1][l - 1][e][0]);
                float4 v0 = q[0], v1 = q[1];
                float2 v2 = *reinterpret_cast<const float2*>(&hio[s & 1][l - 1][e][8]);
                xin[0] = v0.x; xin[1] = v0.y; xin[2] = v0.z; xin[3] = v0.w;
                xin[4] = v1.x; xin[5] = v1.y; xin[6] = v1.z; xin[7] = v1.w;
                xin[8] = v2.x; xin[9] = v2.y;
            }

            // previous hidden state of this layer (all 10 units, written last step)
            float hv[HH];
            {
                const float4* q = reinterpret_cast<const float4*>(&hio[s & 1][l][e][0]);
                float4 v0 = q[0], v1 = q[1];
                float2 v2 = *reinterpret_cast<const float2*>(&hio[s & 1][l][e][8]);
                hv[0] = v0.x; hv[1] = v0.y; hv[2] = v0.z; hv[3] = v0.w;
                hv[4] = v1.x; hv[5] = v1.y; hv[6] = v1.z; hv[7] = v1.w;
                hv[8] = v2.x; hv[9] = v2.y;
            }

            // 4 gate pre-activations for unit u (rows u, u+10, u+20, u+30)
            float g4[4];
#pragma unroll
            for (int gg = 0; gg < 4; ++gg) {
                const float* wr = &sW[l][u + gg * 10][0];
                float4 a0 = *reinterpret_cast<const float4*>(wr);
                float4 a1 = *reinterpret_cast<const float4*>(wr + 4);
                float2 a2 = *reinterpret_cast<const float2*>(wr + 8);
                float4 b0 = *reinterpret_cast<const float4*>(wr + 12);
                float4 b1 = *reinterpret_cast<const float4*>(wr + 16);
                float2 b2 = *reinterpret_cast<const float2*>(wr + 20);
                float s0 = wr[24];   // b_ih + b_hh
                float s1 = 0.0f;
                s0 = fmaf(a0.x, xin[0], s0);  s1 = fmaf(a0.y, xin[1], s1);
                s0 = fmaf(a0.z, xin[2], s0);  s1 = fmaf(a0.w, xin[3], s1);
                s0 = fmaf(a1.x, xin[4], s0);  s1 = fmaf(a1.y, xin[5], s1);
                s0 = fmaf(a1.z, xin[6], s0);  s1 = fmaf(a1.w, xin[7], s1);
                s0 = fmaf(a2.x, xin[8], s0);  s1 = fmaf(a2.y, xin[9], s1);
                s0 = fmaf(b0.x, hv[0], s0);   s1 = fmaf(b0.y, hv[1], s1);
                s0 = fmaf(b0.z, hv[2], s0);   s1 = fmaf(b0.w, hv[3], s1);
                s0 = fmaf(b1.x, hv[4], s0);   s1 = fmaf(b1.y, hv[5], s1);
                s0 = fmaf(b1.z, hv[6], s0);   s1 = fmaf(b1.w, hv[7], s1);
                s0 = fmaf(b2.x, hv[8], s0);   s1 = fmaf(b2.y, hv[9], s1);
                g4[gg] = s0 + s1;
            }

            // torch gate order: i, f, g, o
            const float ig = sigm(g4[0]);
            const float fg = sigm(g4[1]);
            const float gc = tanhx(g4[2]);
            const float og = sigm(g4[3]);
            c = fmaf(fg, c, ig * gc);
            h = og * tanhx(c);

            hio[(s + 1) & 1][l][e][u] = h;

            if (l == LL - 1)
                out[((size_t)t * BB + b) * HH + u] = h;
            if (t == TT - 1) {
                out[base_hn + (size_t)(l * BB + b) * HH + u] = h;
                out[base_cn + (size_t)(l * BB + b) * HH + u] = c;
            }
        }
    }
}

extern "C" void kernel_launch(void* const* d_in, const int* in_sizes, int n_in,
                              void* d_out, int out_size) {
    const float* x   = (const float*)d_in[0];
    const float* hp  = (const float*)d_in[1];
    const float* cp  = (const float*)d_in[2];
    const float* Wih = (const float*)d_in[3];
    const float* Whh = (const float*)d_in[4];
    const float* bih = (const float*)d_in[5];
    const float* bhh = (const float*)d_in[6];
    float* out = (float*)d_out;

    dim3 grid((BB + NB - 1) / NB);   // 342 blocks
    dim3 block(NTH);                 // 320 threads = 10 warps
    lstm_pipe<<<grid, block>>>(x, hp, cp, Wih, Whh, bih, bhh, out);
}

// round 3
// speedup vs baseline: 1.0724x; 1.0724x over previous
#include <cuda_runtime.h>

// PoseLSTM v2.1: register-stationary weights + f32x2 packed math.
//   thread = (layer l, gate-row r); block = 400 threads = 10 layers x 40 rows
//   each thread keeps its row's 20 weights duplicated in f32x2 registers
//   NB=4 batch elements per block -> two packed fma chains per row
//   z ([input;own-h], float4 over e) in SMEM, warp-broadcast reads
//   gate->cell handoff via padded SMEM buffer; 2 syncthreads per step
// Pipeline: layer l processes t = s - l; critical path T+L-1 = 1033 steps.

#define T_ 1024
#define B_ 1024
#define L_ 10
#define H_ 10
#define NB 4
#define NTH 400
#define STEPS (T_ + L_ - 1)

typedef unsigned long long u64;

__device__ __forceinline__ u64 pk2(float lo, float hi) {
    u64 r; asm("mov.b64 %0, {%1,%2};" : "=l"(r) : "f"(lo), "f"(hi)); return r;
}
__device__ __forceinline__ void upk2(u64 v, float& lo, float& hi) {
    asm("mov.b64 {%0,%1}, %2;" : "=f"(lo), "=f"(hi) : "l"(v));
}
__device__ __forceinline__ u64 fma2(u64 a, u64 b, u64 c) {
    u64 d; asm("fma.rn.f32x2 %0, %1, %2, %3;" : "=l"(d) : "l"(a), "l"(b), "l"(c));
    return d;
}
__device__ __forceinline__ float rcpf(float a) {
    float r; asm("rcp.approx.f32 %0, %1;" : "=f"(r) : "f"(a)); return r;
}
__device__ __forceinline__ float ex2f(float a) {
    float r; asm("ex2.approx.f32 %0, %1;" : "=f"(r) : "f"(a)); return r;
}
// branchless activation: v = sA * 1/(1+exp2(K*p)) + sB
//   sigmoid: K=-log2e,  sA=1, sB=0
//   tanh:    K=-2log2e, sA=2, sB=-1
__device__ __forceinline__ float actf(float p, float K, float sA, float sB) {
    float e = ex2f(K * p);
    return fmaf(sA, rcpf(1.0f + e), sB);
}
#define LOG2E 1.4426950408889634f
__device__ __forceinline__ float tanhx(float p) {
    return actf(p, -2.0f * LOG2E, 2.0f, -1.0f);
}

__global__ __launch_bounds__(NTH, 2)
void lstm_pipe2(const float* __restrict__ x,   // (T,B,H)
                const float* __restrict__ hp,  // (L,B,H)
                const float* __restrict__ cp,  // (L,B,H)
                const float* __restrict__ Wih, // (L,4H,H)
                const float* __restrict__ Whh, // (L,4H,H)
                const float* __restrict__ bih, // (L,4H)
                const float* __restrict__ bhh, // (L,4H)
                float* __restrict__ out)       // ys ++ hn ++ cn
{
    // z layout per layer: slots [0..9] = input-from-below, [10..19] = own h. float4 over e.
    __shared__ __align__(16) float4 zall[2][L_][20];   // 6400 B
    __shared__ __align__(16) float4 gbuf[L_][H_][5];   // padded stride 5 -> 3200 B

    const int tid = threadIdx.x;
    const int l = tid / 40;
    const int r = tid % 40;
    const int g = r / 10;          // 0=i 1=f 2=g~ 3=o (torch order)
    const int u = r % 10;
    const int b0 = blockIdx.x * NB;

    // ---- register-stationary weights (duplicated f32x2) ----
    u64 wi2[10], wh2[10];
    {
        const float* wiP = Wih + ((l * 40 + r) * 10);
        const float* whP = Whh + ((l * 40 + r) * 10);
#pragma unroll
        for (int k = 0; k < 10; ++k) {
            float a = __ldg(wiP + k); wi2[k] = pk2(a, a);
            float b = __ldg(whP + k); wh2[k] = pk2(b, b);
        }
    }
    const float bias = bih[l * 40 + r] + bhh[l * 40 + r];
    // per-thread activation constants (uniform per thread -> hoisted)
    const float aK = (g == 2) ? (-2.0f * LOG2E) : (-LOG2E);
    const float aA = (g == 2) ? 2.0f : 1.0f;
    const float aB = (g == 2) ? -1.0f : 0.0f;

    const bool is_cell = (g == 0);
    const bool is_ldr  = (l == 0 && g == 3);

    // ---- init state ----
    float c0 = 0, c1 = 0, c2 = 0, c3 = 0;
    if (is_cell) {
        const float* hpP = hp + ((l * B_ + b0) * H_ + u);
        const float* cpP = cp + ((l * B_ + b0) * H_ + u);
        c0 = cpP[0]; c1 = cpP[10]; c2 = cpP[20]; c3 = cpP[30];
        zall[l & 1][l][10 + u] = make_float4(hpP[0], hpP[10], hpP[20], hpP[30]);
    }
    float xr0 = 0, xr1 = 0, xr2 = 0, xr3 = 0;
    if (is_ldr) {
        const float* xP0 = x + (size_t)b0 * H_ + u;
        zall[0][0][u] = make_float4(xP0[0], xP0[10], xP0[20], xP0[30]);
        const float* xP1 = x + ((size_t)B_ + b0) * H_ + u;
        xr0 = xP1[0]; xr1 = xP1[10]; xr2 = xP1[20]; xr3 = xP1[30];
    }

    const size_t base_hn = (size_t)T_ * B_ * H_;
    const size_t base_cn = base_hn + (size_t)L_ * B_ * H_;

    // ---- wavefront main loop ----
    for (int s = 0; s < STEPS; ++s) {
        const int t = s - l;
        const bool act = ((unsigned)t < (unsigned)T_);
        const ulonglong2* zz =
            reinterpret_cast<const ulonglong2*>(&zall[s & 1][l][0]);
        float4* zw = &zall[(s + 1) & 1][0][0];     // flat [lay*20 + slot]

        __syncthreads();   // A: step s-1 z-writes -> step s z-reads

        if (act) {
            u64 a01 = pk2(bias, bias);
            u64 a23 = a01;
#pragma unroll
            for (int k = 0; k < 10; ++k) {          // input-from-below
                ulonglong2 v = zz[k];
                a01 = fma2(wi2[k], v.x, a01);
                a23 = fma2(wi2[k], v.y, a23);
            }
#pragma unroll
            for (int k = 0; k < 10; ++k) {          // own previous h
                ulonglong2 v = zz[10 + k];
                a01 = fma2(wh2[k], v.x, a01);
                a23 = fma2(wh2[k], v.y, a23);
            }
            float p0, p1, p2, p3;
            upk2(a01, p0, p1); upk2(a23, p2, p3);
            gbuf[l][u][g] = make_float4(actf(p0, aK, aA, aB),
                                        actf(p1, aK, aA, aB),
                                        actf(p2, aK, aA, aB),
                                        actf(p3, aK, aA, aB));
        }
        if (is_ldr && t + 1 < T_) {                 // stage x[t+1]; prefetch x[t+2]
            zw[u] = make_float4(xr0, xr1, xr2, xr3);
            if (t + 2 < T_) {
                const float* xP = x + ((size_t)(t + 2) * B_ + b0) * H_ + u;
                xr0 = xP[0]; xr1 = xP[10]; xr2 = xP[20]; xr3 = xP[30];
            }
        }

        __syncthreads();   // B: gate writes -> cell reads

        if (act && is_cell) {
            float4 I = gbuf[l][u][0];
            float4 F = gbuf[l][u][1];
            float4 G = gbuf[l][u][2];
            float4 O = gbuf[l][u][3];
            c0 = fmaf(F.x, c0, I.x * G.x);
            c1 = fmaf(F.y, c1, I.y * G.y);
            c2 = fmaf(F.z, c2, I.z * G.z);
            c3 = fmaf(F.w, c3, I.w * G.w);
            float h0 = O.x * tanhx(c0);
            float h1 = O.y * tanhx(c1);
            float h2 = O.z * tanhx(c2);
            float h3 = O.w * tanhx(c3);
            float4 hv = make_float4(h0, h1, h2, h3);
            zw[l * 20 + 10 + u] = hv;               // own h for next step
            if (l < L_ - 1) {
                zw[(l + 1) * 20 + u] = hv;          // input for layer above
            } else {
                float* oP = out + ((size_t)t * B_ + b0) * H_ + u;
                oP[0] = h0; oP[10] = h1; oP[20] = h2; oP[30] = h3;
            }
            if (t == T_ - 1) {
                float* hnP = out + base_hn + ((size_t)l * B_ + b0) * H_ + u;
                float* cnP = out + base_cn + ((size_t)l * B_ + b0) * H_ + u;
                hnP[0] = h0; hnP[10] = h1; hnP[20] = h2; hnP[30] = h3;
                cnP[0] = c0; cnP[10] = c1; cnP[20] = c2; cnP[30] = c3;
            }
        }
    }
}

extern "C" void kernel_launch(void* const* d_in, const int* in_sizes, int n_in,
                              void* d_out, int out_size) {
    const float* x   = (const float*)d_in[0];
    const float* hp  = (const float*)d_in[1];
    const float* cp  = (const float*)d_in[2];
    const float* Wih = (const float*)d_in[3];
    const float* Whh = (const float*)d_in[4];
    const float* bih = (const float*)d_in[5];
    const float* bhh = (const float*)d_in[6];
    float* out = (float*)d_out;

    dim3 grid(B_ / NB);   // 256 blocks
    dim3 block(NTH);      // 400 threads = 10 layers x 40 rows
    lstm_pipe2<<<grid, block>>>(x, hp, cp, Wih, Whh, bih, bhh, out);
}

// round 4
// speedup vs baseline: 1.8234x; 1.7004x over previous
#include <cuda_runtime.h>

// PoseLSTM v3: wavefront pipeline, gate-quad shuffles, MUFU.TANH, 1 barrier/step.
//   block = 400 threads = 10 layers x 40 rows; thread = (l, u, g), r = u*4+g
//   gate quad (u) = 4 consecutive lanes -> butterfly shfl exchange, no gbuf/barrier B
//   weights register-stationary as dup'd f32x2; gates = 40x fma.rn.f32x2 (NB=4)
//   z double buffer in SMEM, parity unrolled -> immediate-offset LDS/STS
//   activations: v = cA + cB*tanh(cS*p) via tanh.approx.f32 (sigmoid & tanh unified)

#define T_ 1024
#define B_ 1024
#define L_ 10
#define H_ 10
#define NB 4
#define NTH 400

typedef unsigned long long u64;

__device__ __forceinline__ u64 pk2(float lo, float hi) {
    u64 r; asm("mov.b64 %0, {%1,%2};" : "=l"(r) : "f"(lo), "f"(hi)); return r;
}
__device__ __forceinline__ void upk2(u64 v, float& lo, float& hi) {
    asm("mov.b64 {%0,%1}, %2;" : "=f"(lo), "=f"(hi) : "l"(v));
}
__device__ __forceinline__ u64 fma2(u64 a, u64 b, u64 c) {
    u64 d; asm("fma.rn.f32x2 %0, %1, %2, %3;" : "=l"(d) : "l"(a), "l"(b), "l"(c));
    return d;
}
__device__ __forceinline__ float tanhap(float x) {
    float r; asm("tanh.approx.f32 %0, %1;" : "=f"(r) : "f"(x)); return r;
}

// one element's gate-exchange + cell update (runs in all 4 lanes of the quad)
__device__ __forceinline__ void cellstep(float p, float& c, float& h,
                                         float cS, float cA, float cB,
                                         int g, unsigned mask, bool act) {
    float v  = fmaf(cB, tanhap(cS * p), cA);        // own activated gate
    float Bv = __shfl_xor_sync(mask, v, 1);         // partner within pair
    float X  = (g & 1) ? Bv : v;                    // {i | g~} of this pair
    float Y  = (g & 1) ? v  : Bv;                   // {f | o}  of this pair
    float Xo = __shfl_xor_sync(mask, X, 2);         // other pair's X
    float Yo = __shfl_xor_sync(mask, Y, 2);         // other pair's Y
    float F  = (g & 2) ? Yo : Y;                    // sigma(f)
    float O  = (g & 2) ? Y  : Yo;                   // sigma(o)
    float ig = X * Xo;                              // sigma(i)*tanh(g~)
    if (act) c = fmaf(F, c, ig);                    // predicated state update
    h = O * tanhap(c);                              // garbage when !act (stores gated)
}

__global__ __launch_bounds__(NTH, 2)
void lstm_pipe3(const float* __restrict__ x,   // (T,B,H)
                const float* __restrict__ hp,  // (L,B,H)
                const float* __restrict__ cp,  // (L,B,H)
                const float* __restrict__ Wih, // (L,4H,H)
                const float* __restrict__ Whh, // (L,4H,H)
                const float* __restrict__ bih, // (L,4H)
                const float* __restrict__ bhh, // (L,4H)
                float* __restrict__ out)       // ys ++ hn ++ cn
{
    // z[buf][layer][slot]: slot 0..9 = input-from-below, 10..19 = own h; float4 over e.
    // layer row L_ (10) is a write-sink for layer 9's "above" store.
    __shared__ __align__(16) float4 z[2][L_ + 1][20];   // 7040 B

    const int tid = threadIdx.x;
    const int l = tid / 40;
    const int r = tid % 40;
    const int u = r >> 2;          // unit 0..9
    const int g = r & 3;           // gate 0=i 1=f 2=g~ 3=o (torch order)
    const int b0 = blockIdx.x * NB;
    const unsigned mask = (tid < 384) ? 0xFFFFFFFFu : 0x0000FFFFu;  // last warp = 16 lanes

    // ---- register-stationary weights for row (g*10+u), duplicated f32x2 ----
    const int row = l * 40 + g * 10 + u;
    u64 wi2[10], wh2[10];
    {
        const float* wiP = Wih + row * 10;
        const float* whP = Whh + row * 10;
#pragma unroll
        for (int k = 0; k < 10; ++k) {
            float a = __ldg(wiP + k); wi2[k] = pk2(a, a);
            float b = __ldg(whP + k); wh2[k] = pk2(b, b);
        }
    }
    const float bsum = bih[row] + bhh[row];
    const u64 bias2 = pk2(bsum, bsum);

    // unified activation constants: sigmoid -> (0.5,0.5,0.5); tanh(g~) -> (1,0,1)
    const float cS = (g == 2) ? 1.0f : 0.5f;
    const float cA = (g == 2) ? 0.0f : 0.5f;
    const float cB = (g == 2) ? 1.0f : 0.5f;

    // ---- init state ----
    float c0 = 0, c1 = 0, c2 = 0, c3 = 0;
    if (g == 0) {
        const float* hpP = hp + ((l * B_ + b0) * H_ + u);
        const float* cpP = cp + ((l * B_ + b0) * H_ + u);
        c0 = cpP[0]; c1 = cpP[10]; c2 = cpP[20]; c3 = cpP[30];
        z[l & 1][l][10 + u] = make_float4(hpP[0], hpP[10], hpP[20], hpP[30]);
    }
    // broadcast c to the whole quad (all lanes carry c redundantly)
    c0 = __shfl_sync(mask, c0, (r & ~3) + 0 - (r - (tid & 31)) >= 0 ? ((tid & 31) & ~3) : 0, 32);
    // (the above is wrong-prone; do it simply below)
    {
        int qbase = (tid & 31) & ~3;   // quad base lane within warp
        c0 = __shfl_sync(mask, c0, qbase, 32);
        c1 = __shfl_sync(mask, c1, qbase, 32);
        c2 = __shfl_sync(mask, c2, qbase, 32);
        c3 = __shfl_sync(mask, c3, qbase, 32);
    }
    float h0 = 0, h1 = 0, h2 = 0, h3 = 0;

    const bool isLdr = (l == 0 && g == 3);
    if (isLdr) {
        const float* xp = x + (size_t)b0 * H_ + u;
        z[0][0][u] = make_float4(xp[0], xp[10], xp[20], xp[30]);
    }

    // unified h-store target: g0 -> own h slot, g1 -> layer-above input slot
    const int stL    = (g == 0) ? l : (l + 1);
    const int stSlot = (g == 0) ? (10 + u) : u;
    const bool doStH = (g < 2);
    const bool isOut = (g == 2 && l == L_ - 1);

    const size_t base_hn = (size_t)T_ * B_ * H_;
    const size_t base_cn = base_hn + (size_t)L_ * B_ * H_;

    // ---- wavefront main loop, parity-unrolled ----
    for (int s0 = 0; s0 < 1034; s0 += 2) {
#pragma unroll
        for (int par = 0; par < 2; ++par) {
            const int scur = s0 + par;
            const int t = scur - l;
            const bool act = ((unsigned)t < (unsigned)T_);

            // layer-0 x load for t+1 (global, before barrier; latency covered by step)
            float xl0, xl1, xl2, xl3;
            const bool ldrGo = isLdr && (scur + 1 < T_);
            if (ldrGo) {
                const float* xp = x + ((size_t)(scur + 1) * B_ + b0) * H_ + u;
                xl0 = xp[0]; xl1 = xp[10]; xl2 = xp[20]; xl3 = xp[30];
            }

            __syncthreads();   // step s-1 z-writes -> step s z-reads

            const ulonglong2* zz = reinterpret_cast<const ulonglong2*>(&z[par][l][0]);
            u64 a01 = bias2, a23 = bias2;
#pragma unroll
            for (int k = 0; k < 10; ++k) {
                ulonglong2 vv = zz[k];
                a01 = fma2(wi2[k], vv.x, a01);
                a23 = fma2(wi2[k], vv.y, a23);
            }
#pragma unroll
            for (int k = 0; k < 10; ++k) {
                ulonglong2 vv = zz[10 + k];
                a01 = fma2(wh2[k], vv.x, a01);
                a23 = fma2(wh2[k], vv.y, a23);
            }
            float p0, p1, p2, p3;
            upk2(a01, p0, p1); upk2(a23, p2, p3);

            cellstep(p0, c0, h0, cS, cA, cB, g, mask, act);
            cellstep(p1, c1, h1, cS, cA, cB, g, mask, act);
            cellstep(p2, c2, h2, cS, cA, cB, g, mask, act);
            cellstep(p3, c3, h3, cS, cA, cB, g, mask, act);

            // h handoff (single predicated STS.128; l=9's g1 hits dummy row 10)
            if (act && doStH)
                z[par ^ 1][stL][stSlot] = make_float4(h0, h1, h2, h3);

            if (act && isOut) {
                float* oP = out + ((size_t)t * B_ + b0) * H_ + u;
                oP[0] = h0; oP[10] = h1; oP[20] = h2; oP[30] = h3;
            }
            if (act && t == T_ - 1) {
                if (g == 2) {
                    float* hnP = out + base_hn + ((size_t)l * B_ + b0) * H_ + u;
                    hnP[0] = h0; hnP[10] = h1; hnP[20] = h2; hnP[30] = h3;
                } else if (g == 3) {
                    float* cnP = out + base_cn + ((size_t)l * B_ + b0) * H_ + u;
                    cnP[0] = c0; cnP[10] = c1; cnP[20] = c2; cnP[30] = c3;
                }
            }
            if (ldrGo)
                z[par ^ 1][0][u] = make_float4(xl0, xl1, xl2, xl3);
        }
    }
}

extern "C" void kernel_launch(void* const* d_in, const int* in_sizes, int n_in,
                              void* d_out, int out_size) {
    const float* x   = (const float*)d_in[0];
    const float* hp  = (const float*)d_in[1];
    const float* cp  = (const float*)d_in[2];
    const float* Wih = (const float*)d_in[3];
    const float* Whh = (const float*)d_in[4];
    const float* bih = (const float*)d_in[5];
    const float* bhh = (const float*)d_in[6];
    float* out = (float*)d_out;

    dim3 grid(B_ / NB);   // 256 blocks
    dim3 block(NTH);      // 400 threads
    lstm_pipe3<<<grid, block>>>(x, hp, cp, Wih, Whh, bih, bhh, out);
}

// round 5
// speedup vs baseline: 1.9962x; 1.0948x over previous
#include <cuda_runtime.h>

// PoseLSTM v4: wavefront + quad-gather shuffles + folded sigmoid scaling.
//   block = 400 threads = 10 layers x 40 rows; thread = (l, u, g), r = u*4+g
//   gate exchange: 4 shfl.idx per element from the 4-aligned quad (no SELs)
//   sigmoid(z) = 0.5 + 0.5*tanh(0.5*z): the 0.5 pre-folded into W and bias
//   weights register-stationary dup'd f32x2; 4 accumulation chains for ILP
//   z double buffer in SMEM, parity unrolled; 1 syncthreads per step

#define T_ 1024
#define B_ 1024
#define L_ 10
#define H_ 10
#define NB 4
#define NTH 400

typedef unsigned long long u64;

__device__ __forceinline__ u64 pk2(float lo, float hi) {
    u64 r; asm("mov.b64 %0, {%1,%2};" : "=l"(r) : "f"(lo), "f"(hi)); return r;
}
__device__ __forceinline__ void upk2(u64 v, float& lo, float& hi) {
    asm("mov.b64 {%0,%1}, %2;" : "=f"(lo), "=f"(hi) : "l"(v));
}
__device__ __forceinline__ u64 fma2(u64 a, u64 b, u64 c) {
    u64 d; asm("fma.rn.f32x2 %0, %1, %2, %3;" : "=l"(d) : "l"(a), "l"(b), "l"(c));
    return d;
}
__device__ __forceinline__ u64 add2(u64 a, u64 b) {
    u64 d; asm("add.rn.f32x2 %0, %1, %2;" : "=l"(d) : "l"(a), "l"(b));
    return d;
}
__device__ __forceinline__ float tanhap(float x) {
    float r; asm("tanh.approx.f32 %0, %1;" : "=f"(r) : "f"(x)); return r;
}

__global__ __launch_bounds__(NTH, 2)
void lstm_pipe4(const float* __restrict__ x,   // (T,B,H)
                const float* __restrict__ hp,  // (L,B,H)
                const float* __restrict__ cp,  // (L,B,H)
                const float* __restrict__ Wih, // (L,4H,H)
                const float* __restrict__ Whh, // (L,4H,H)
                const float* __restrict__ bih, // (L,4H)
                const float* __restrict__ bhh, // (L,4H)
                float* __restrict__ out)       // ys ++ hn ++ cn
{
    // z[buf][layer][slot]: 0..9 input-from-below, 10..19 own h; float4 over e.
    // row L_ is a write sink for layer 9's "above" store.
    __shared__ __align__(16) float4 z[2][L_ + 1][20];

    const int tid = threadIdx.x;
    const int l = tid / 40;
    const int r = tid % 40;
    const int u = r >> 2;          // unit 0..9
    const int g = r & 3;           // gate 0=i 1=f 2=g~ 3=o (torch order)
    const int b0 = blockIdx.x * NB;
    const int lane = tid & 31;
    const unsigned mask = (tid < 384) ? 0xFFFFFFFFu : 0x0000FFFFu;
    const int qb = lane & ~3;      // quad base lane
    const int q0 = qb, q1 = qb | 1, q2 = qb | 2, q3 = qb | 3;

    // ---- register-stationary weights, sigmoid gates pre-scaled by 0.5 ----
    const int row = l * 40 + g * 10 + u;
    const float wscl = (g == 2) ? 1.0f : 0.5f;
    u64 wi2[10], wh2[10];
    {
        const float* wiP = Wih + row * 10;
        const float* whP = Whh + row * 10;
#pragma unroll
        for (int k = 0; k < 10; ++k) {
            float a = wscl * __ldg(wiP + k); wi2[k] = pk2(a, a);
            float b = wscl * __ldg(whP + k); wh2[k] = pk2(b, b);
        }
    }
    const float bsum = wscl * (bih[row] + bhh[row]);
    const u64 bias2 = pk2(bsum, bsum);
    // activation: v = cA + cB * tanh(p_scaled);  sigmoid->(0.5,0.5), tanh->(0,1)
    const float cA = (g == 2) ? 0.0f : 0.5f;
    const float cB = (g == 2) ? 1.0f : 0.5f;

    // ---- init state (c broadcast to whole quad) ----
    float c0 = 0, c1 = 0, c2 = 0, c3 = 0;
    if (g == 0) {
        const float* hpP = hp + ((l * B_ + b0) * H_ + u);
        const float* cpP = cp + ((l * B_ + b0) * H_ + u);
        c0 = cpP[0]; c1 = cpP[10]; c2 = cpP[20]; c3 = cpP[30];
        z[l & 1][l][10 + u] = make_float4(hpP[0], hpP[10], hpP[20], hpP[30]);
    }
    c0 = __shfl_sync(mask, c0, q0);
    c1 = __shfl_sync(mask, c1, q0);
    c2 = __shfl_sync(mask, c2, q0);
    c3 = __shfl_sync(mask, c3, q0);
    float h0 = 0, h1 = 0, h2 = 0, h3 = 0;

    const bool isLdr = (l == 0 && g == 3);
    if (isLdr) {
        const float* xp = x + (size_t)b0 * H_ + u;
        z[0][0][u] = make_float4(xp[0], xp[10], xp[20], xp[30]);
    }

    // unified h-store: g0 -> own h slot, g1 -> layer-above input slot
    const int stL    = (g == 0) ? l : (l + 1);
    const int stSlot = (g == 0) ? (10 + u) : u;
    const bool doStH = (g < 2);
    const bool isOut = (g == 2 && l == L_ - 1);

    const size_t base_hn = (size_t)T_ * B_ * H_;
    const size_t base_cn = base_hn + (size_t)L_ * B_ * H_;

    // ---- wavefront main loop, parity-unrolled ----
    for (int s0 = 0; s0 < 1034; s0 += 2) {
#pragma unroll
        for (int par = 0; par < 2; ++par) {
            const int scur = s0 + par;
            const int t = scur - l;
            const bool act = ((unsigned)t < (unsigned)T_);

            // layer-0 x load for t+1 (issued before barrier to cover latency)
            float xl0, xl1, xl2, xl3;
            const bool ldrGo = isLdr && (scur + 1 < T_);
            if (ldrGo) {
                const float* xp = x + ((size_t)(scur + 1) * B_ + b0) * H_ + u;
                xl0 = xp[0]; xl1 = xp[10]; xl2 = xp[20]; xl3 = xp[30];
            }

            __syncthreads();   // step s-1 z-writes -> step s z-reads

            // ---- matvec: 4 independent f32x2 chains ----
            const ulonglong2* zz = reinterpret_cast<const ulonglong2*>(&z[par][l][0]);
            u64 aA = bias2, aB = pk2(0.0f, 0.0f);
            u64 bA = bias2, bB = pk2(0.0f, 0.0f);
#pragma unroll
            for (int k = 0; k < 5; ++k) {
                ulonglong2 v0 = zz[2 * k];
                ulonglong2 v1 = zz[2 * k + 1];
                aA = fma2(wi2[2 * k],     v0.x, aA);
                bA = fma2(wi2[2 * k],     v0.y, bA);
                aB = fma2(wi2[2 * k + 1], v1.x, aB);
                bB = fma2(wi2[2 * k + 1], v1.y, bB);
            }
#pragma unroll
            for (int k = 0; k < 5; ++k) {
                ulonglong2 v0 = zz[10 + 2 * k];
                ulonglong2 v1 = zz[10 + 2 * k + 1];
                aA = fma2(wh2[2 * k],     v0.x, aA);
                bA = fma2(wh2[2 * k],     v0.y, bA);
                aB = fma2(wh2[2 * k + 1], v1.x, aB);
                bB = fma2(wh2[2 * k + 1], v1.y, bB);
            }
            u64 a01 = add2(aA, aB);
            u64 a23 = add2(bA, bB);
            float p0, p1, p2, p3;
            upk2(a01, p0, p1); upk2(a23, p2, p3);

            // ---- activation (scale already folded into weights) ----
            float v0 = fmaf(cB, tanhap(p0), cA);
            float v1 = fmaf(cB, tanhap(p1), cA);
            float v2 = fmaf(cB, tanhap(p2), cA);
            float v3 = fmaf(cB, tanhap(p3), cA);

            // ---- quad gather: 4 shfl per element, no selects ----
            float i0 = __shfl_sync(mask, v0, q0), f0 = __shfl_sync(mask, v0, q1),
                  G0 = __shfl_sync(mask, v0, q2), o0 = __shfl_sync(mask, v0, q3);
            float i1 = __shfl_sync(mask, v1, q0), f1 = __shfl_sync(mask, v1, q1),
                  G1 = __shfl_sync(mask, v1, q2), o1 = __shfl_sync(mask, v1, q3);
            float i2 = __shfl_sync(mask, v2, q0), f2 = __shfl_sync(mask, v2, q1),
                  G2 = __shfl_sync(mask, v2, q2), o2 = __shfl_sync(mask, v2, q3);
            float i3 = __shfl_sync(mask, v3, q0), f3 = __shfl_sync(mask, v3, q1),
                  G3 = __shfl_sync(mask, v3, q2), o3 = __shfl_sync(mask, v3, q3);

            // ---- cell update (redundant in all 4 lanes; predicated on act) ----
            if (act) {
                c0 = fmaf(f0, c0, i0 * G0);
                c1 = fmaf(f1, c1, i1 * G1);
                c2 = fmaf(f2, c2, i2 * G2);
                c3 = fmaf(f3, c3, i3 * G3);
            }
            h0 = o0 * tanhap(c0);
            h1 = o1 * tanhap(c1);
            h2 = o2 * tanhap(c2);
            h3 = o3 * tanhap(c3);

            // ---- h handoff (single predicated STS.128; l=9 g1 hits sink row) ----
            if (act && doStH)
                z[par ^ 1][stL][stSlot] = make_float4(h0, h1, h2, h3);

            if (act && isOut) {
                float* oP = out + ((size_t)t * B_ + b0) * H_ + u;
                oP[0] = h0; oP[10] = h1; oP[20] = h2; oP[30] = h3;
            }
            if (act && t == T_ - 1) {
                if (g == 2) {
                    float* hnP = out + base_hn + ((size_t)l * B_ + b0) * H_ + u;
                    hnP[0] = h0; hnP[10] = h1; hnP[20] = h2; hnP[30] = h3;
                } else if (g == 3) {
                    float* cnP = out + base_cn + ((size_t)l * B_ + b0) * H_ + u;
                    cnP[0] = c0; cnP[10] = c1; cnP[20] = c2; cnP[30] = c3;
                }
            }
            if (ldrGo)
                z[par ^ 1][0][u] = make_float4(xl0, xl1, xl2, xl3);
        }
    }
}

extern "C" void kernel_launch(void* const* d_in, const int* in_sizes, int n_in,
                              void* d_out, int out_size) {
    const float* x   = (const float*)d_in[0];
    const float* hp  = (const float*)d_in[1];
    const float* cp  = (const float*)d_in[2];
    const float* Wih = (const float*)d_in[3];
    const float* Whh = (const float*)d_in[4];
    const float* bih = (const float*)d_in[5];
    const float* bhh = (const float*)d_in[6];
    float* out = (float*)d_out;

    dim3 grid(B_ / NB);   // 256 blocks
    dim3 block(NTH);      // 400 threads
    lstm_pipe4<<<grid, block>>>(x, hp, cp, Wih, Whh, bih, bhh, out);
}

// round 6
// speedup vs baseline: 2.1135x; 1.0588x over previous
#include <cuda_runtime.h>

// PoseLSTM v5: gate-pair threads, k-packed f32x2, minimal MIO.
//   block = 800 threads = 10 layers x (10 units x 4 elems x 2 gate-pairs)
//   thread computes 2 gate rows (i,f | g,o) for ONE element over 20 dims:
//     20x fma.rn.f32x2 on (z2k,z2k+1) pairs direct from LDS.128 (no dup movs)
//   pair exchange: 2 shfl.xor(1); i*g is lane-symmetric; f/o via 2 selects
//   z per (layer, elem): 20 contiguous floats (input 0-9, own h 10-19), stride 24
//   1 syncthreads/step, parity-unrolled double buffer. 256 blocks, 1 block/SM.

#define T_ 1024
#define B_ 1024
#define L_ 10
#define H_ 10
#define NB 4
#define NTH 800

typedef unsigned long long u64;

__device__ __forceinline__ u64 pk2(float lo, float hi) {
    u64 r; asm("mov.b64 %0, {%1,%2};" : "=l"(r) : "f"(lo), "f"(hi)); return r;
}
__device__ __forceinline__ void upk2(u64 v, float& lo, float& hi) {
    asm("mov.b64 {%0,%1}, %2;" : "=f"(lo), "=f"(hi) : "l"(v));
}
__device__ __forceinline__ u64 fma2(u64 a, u64 b, u64 c) {
    u64 d; asm("fma.rn.f32x2 %0, %1, %2, %3;" : "=l"(d) : "l"(a), "l"(b), "l"(c));
    return d;
}
__device__ __forceinline__ u64 add2(u64 a, u64 b) {
    u64 d; asm("add.rn.f32x2 %0, %1, %2;" : "=l"(d) : "l"(a), "l"(b));
    return d;
}
__device__ __forceinline__ float tanhap(float x) {
    float r; asm("tanh.approx.f32 %0, %1;" : "=f"(r) : "f"(x)); return r;
}

__global__ __launch_bounds__(NTH, 1)
void lstm_pipe5(const float* __restrict__ x,   // (T,B,H)
                const float* __restrict__ hp,  // (L,B,H)
                const float* __restrict__ cp,  // (L,B,H)
                const float* __restrict__ Wih, // (L,4H,H)
                const float* __restrict__ Whh, // (L,4H,H)
                const float* __restrict__ bih, // (L,4H)
                const float* __restrict__ bhh, // (L,4H)
                float* __restrict__ out)       // ys ++ hn ++ cn
{
    // z[buf][layer][elem][24]: slots 0..9 input-from-below, 10..19 own h.
    // stride 24 floats (96B) -> the 4 elem rows hit disjoint bank groups.
    __shared__ __align__(16) float z[2][L_ + 1][NB][24];   // 8448 B

    const int tid = threadIdx.x;
    const int l  = tid / 80;
    const int r  = tid % 80;           // u*8 + e*2 + gp
    const int u  = r >> 3;
    const int e  = (r >> 1) & 3;
    const int gp = r & 1;              // 0: gates (i,f)   1: gates (g~,o)
    const int b  = blockIdx.x * NB + e;

    // ---- k-packed register-stationary weights, sigmoid scale 0.5 folded ----
    // rowA = gate i (gp0) or g~ (gp1); rowB = gate f (gp0) or o (gp1)
    const int rowA = l * 40 + gp * 20 + u;
    const int rowB = rowA + 10;
    const float sclA = gp ? 1.0f : 0.5f;    // g~ is tanh (unscaled), i is sigmoid
    u64 wA[10], wB[10];
    {
        const float* WiA = Wih + rowA * 10; const float* WhA = Whh + rowA * 10;
        const float* WiB = Wih + rowB * 10; const float* WhB = Whh + rowB * 10;
#pragma unroll
        for (int k = 0; k < 5; ++k) {
            wA[k]     = pk2(sclA * __ldg(WiA + 2 * k), sclA * __ldg(WiA + 2 * k + 1));
            wA[5 + k] = pk2(sclA * __ldg(WhA + 2 * k), sclA * __ldg(WhA + 2 * k + 1));
            wB[k]     = pk2(0.5f * __ldg(WiB + 2 * k), 0.5f * __ldg(WiB + 2 * k + 1));
            wB[5 + k] = pk2(0.5f * __ldg(WhB + 2 * k), 0.5f * __ldg(WhB + 2 * k + 1));
        }
    }
    const float biasA = sclA * (bih[rowA] + bhh[rowA]);
    const float biasB = 0.5f * (bih[rowB] + bhh[rowB]);
    // activation A: gp0 sigmoid (0.5 + 0.5*th), gp1 tanh (0 + 1*th)
    const float cAa = gp ? 0.0f : 0.5f;
    const float cBa = gp ? 1.0f : 0.5f;

    // ---- init state (c held redundantly in both pair lanes) ----
    float c = cp[(l * B_ + b) * H_ + u];
    float h;
    if (gp == 0)
        z[l & 1][l][e][10 + u] = hp[(l * B_ + b) * H_ + u];
    const bool isLdr = (l == 0 && gp == 0);
    if (isLdr)
        z[0][0][e][u] = x[(size_t)b * H_ + u];

    const size_t base_hn = (size_t)T_ * B_ * H_;
    const size_t base_cn = base_hn + (size_t)L_ * B_ * H_;

    // ---- wavefront main loop, parity-unrolled ----
    for (int s0 = 0; s0 < 1034; s0 += 2) {
#pragma unroll
        for (int par = 0; par < 2; ++par) {
            const int scur = s0 + par;
            const int t = scur - l;
            const bool act = ((unsigned)t < (unsigned)T_);

            float xl;
            const bool ldrGo = isLdr && (scur + 1 < T_);
            if (ldrGo)
                xl = x[((size_t)(scur + 1) * B_ + b) * H_ + u];

            __syncthreads();   // step s-1 z-writes -> step s z-reads

            // ---- matvec: 4 independent k-packed chains, 5 LDS.128 total ----
            const ulonglong2* zz =
                reinterpret_cast<const ulonglong2*>(&z[par][l][e][0]);
            u64 aA = pk2(biasA, 0.0f), aA2 = pk2(0.0f, 0.0f);
            u64 aB = pk2(biasB, 0.0f), aB2 = pk2(0.0f, 0.0f);
#pragma unroll
            for (int m = 0; m < 5; ++m) {
                ulonglong2 v = zz[m];
                aA  = fma2(wA[2 * m],     v.x, aA);
                aA2 = fma2(wA[2 * m + 1], v.y, aA2);
                aB  = fma2(wB[2 * m],     v.x, aB);
                aB2 = fma2(wB[2 * m + 1], v.y, aB2);
            }
            u64 sA = add2(aA, aA2), sB = add2(aB, aB2);
            float pA, pAh, pB, pBh;
            upk2(sA, pA, pAh); upk2(sB, pB, pBh);
            pA += pAh; pB += pBh;

            // ---- activations (scales folded into weights) ----
            float vA = fmaf(cBa,  tanhap(pA), cAa);   // gp0: sig(i), gp1: tanh(g~)
            float vB = fmaf(0.5f, tanhap(pB), 0.5f);  // gp0: sig(f), gp1: sig(o)

            // ---- pair exchange: 2 shfl, 2 sel ----
            float Ao = __shfl_xor_sync(0xFFFFFFFFu, vA, 1);
            float Bo = __shfl_xor_sync(0xFFFFFFFFu, vB, 1);
            float F = gp ? Bo : vB;
            float O = gp ? vB : Bo;
            if (act) c = fmaf(F, c, vA * Ao);    // i*g~ is lane-symmetric
            h = O * tanhap(c);

            // ---- h handoff / outputs ----
            if (act) {
                if (gp == 0) {
                    z[par ^ 1][l][e][10 + u] = h;         // own h
                } else if (l < L_ - 1) {
                    z[par ^ 1][l + 1][e][u] = h;          // input for layer above
                } else {
                    out[((size_t)t * B_ + b) * H_ + u] = h;   // ys
                }
                if (t == T_ - 1) {
                    if (gp == 0)
                        out[base_hn + ((size_t)l * B_ + b) * H_ + u] = h;
                    else
                        out[base_cn + ((size_t)l * B_ + b) * H_ + u] = c;
                }
            }
            if (ldrGo)
                z[par ^ 1][0][e][u] = xl;
        }
    }
}

extern "C" void kernel_launch(void* const* d_in, const int* in_sizes, int n_in,
                              void* d_out, int out_size) {
    const float* x   = (const float*)d_in[0];
    const float* hp  = (const float*)d_in[1];
    const float* cp  = (const float*)d_in[2];
    const float* Wih = (const float*)d_in[3];
    const float* Whh = (const float*)d_in[4];
    const float* bih = (const float*)d_in[5];
    const float* bhh = (const float*)d_in[6];
    float* out = (float*)d_out;

    dim3 grid(B_ / NB);   // 256 blocks
    dim3 block(NTH);      // 800 threads = 25 full warps
    lstm_pipe5<<<grid, block>>>(x, hp, cp, Wih, Whh, bih, bhh, out);
}